// round 12
// baseline (speedup 1.0000x reference)
#include <cuda_runtime.h>
#include <math.h>

// Problem constants
#define Bq  4
#define Sq  1024
#define Dq  2048
#define Hh  16
#define DHh 128
#define MSZ (Bq*Sq)          // 4096 rows
#define SCALE_F 11.3137084989847603904f   // sqrt(128)

// Scratch (allocation-free rule: __device__ globals)
__device__ float g_q[MSZ*Dq];
__device__ float g_k[MSZ*Dq];
__device__ float g_v[MSZ*Dq];
__device__ float g_ctx[MSZ*Dq];

// ---------------------------------------------------------------------------
// Packed fp32x2 helpers (Blackwell sm_10x; exact fp32 semantics per lane).
// fma.rn.f32x2: d.lo = a.lo*b.lo + c.lo ; d.hi = a.hi*b.hi + c.hi
// ---------------------------------------------------------------------------
__device__ __forceinline__ unsigned long long pack2_bcast(float v) {
    unsigned long long r;
    asm("mov.b64 %0, {%1, %1};" : "=l"(r) : "f"(v));
    return r;
}
__device__ __forceinline__ void ffma2(unsigned long long& d,
                                      unsigned long long a,
                                      unsigned long long b) {
    asm("fma.rn.f32x2 %0, %1, %2, %0;" : "+l"(d) : "l"(a), "l"(b));
}
__device__ __forceinline__ unsigned long long mul2(unsigned long long a,
                                                   unsigned long long b) {
    unsigned long long d;
    asm("mul.rn.f32x2 %0, %1, %2;" : "=l"(d) : "l"(a), "l"(b));
    return d;
}
__device__ __forceinline__ float2 unpack2(unsigned long long v) {
    float lo, hi;
    asm("mov.b64 {%0, %1}, %2;" : "=f"(lo), "=f"(hi) : "l"(v));
    return make_float2(lo, hi);
}
__device__ __forceinline__ void prefetch_l2(const void* p) {
    asm volatile("prefetch.global.L2 [%0];" :: "l"(p));
}

// ---------------------------------------------------------------------------
// Core SGEMM NT tile: C[M,N] = A[M,K] * B[N,K]^T  (row-major, K contiguous)
// 128x128 block tile, BK=16, 256 threads, 8x8 per-thread microtile.
// Double-buffered smem ping-pong (one __syncthreads per k-tile).
// A tile stored DUPLICATED in smem (As[k][2m],As[k][2m+1]=A[m]; 256-f rows):
// one LDS.128 yields two ready-packed (a,a) f32x2 operands -> the inner loop
// is 32 FFMA2 + 6 LDS.128 per kk with ZERO pack MOVs.
// A-LDS address depends only on ty -> broadcast, conflict-free.
// ---------------------------------------------------------------------------
__device__ __forceinline__ void sgemm_tile(const float* __restrict__ A,
                                           const float* __restrict__ Bw,
                                           float* __restrict__ C,
                                           int M, int N, int K,
                                           int tm, int tn,
                                           float (*As)[16*256], float (*Bs)[16*128])
{
    const int tid = threadIdx.x;
    const int ty  = tid >> 4;
    const int tx  = tid & 15;

    // Loader mapping: 512 float4 per tile per matrix; 2 per thread.
    const int lin0 = tid;
    const int lin1 = tid + 256;
    const int mr0 = lin0 >> 2, kc0 = (lin0 & 3) << 2;
    const int mr1 = lin1 >> 2, kc1 = (lin1 & 3) << 2;

    const float* Ap0 = A  + (size_t)(tm + mr0) * K + kc0;
    const float* Ap1 = A  + (size_t)(tm + mr1) * K + kc1;
    const float* Bp0 = Bw + (size_t)(tn + mr0) * K + kc0;
    const float* Bp1 = Bw + (size_t)(tn + mr1) * K + kc1;

    // 8 rows x 4 column-pairs (cols tx*4..+3 and 64+tx*4..+3), packed f32x2.
    unsigned long long acc[8][4];
#pragma unroll
    for (int r = 0; r < 8; ++r)
#pragma unroll
        for (int p = 0; p < 4; ++p) acc[r][p] = 0ull;   // (0.f,0.f)

    // Prefetch tile 0 into registers
    float4 pa0 = *(const float4*)Ap0;
    float4 pa1 = *(const float4*)Ap1;
    float4 pb0 = *(const float4*)Bp0;
    float4 pb1 = *(const float4*)Bp1;

    const int ntk = K >> 4;
    int buf = 0;
    {
        float2* d2;
        float*  d;
        d2 = (float2*)&As[0][kc0*256 + mr0*2];
        d2[0]   = make_float2(pa0.x, pa0.x); d2[128] = make_float2(pa0.y, pa0.y);
        d2[256] = make_float2(pa0.z, pa0.z); d2[384] = make_float2(pa0.w, pa0.w);
        d2 = (float2*)&As[0][kc1*256 + mr1*2];
        d2[0]   = make_float2(pa1.x, pa1.x); d2[128] = make_float2(pa1.y, pa1.y);
        d2[256] = make_float2(pa1.z, pa1.z); d2[384] = make_float2(pa1.w, pa1.w);
        d = &Bs[0][kc0*128 + mr0]; d[0]=pb0.x; d[128]=pb0.y; d[256]=pb0.z; d[384]=pb0.w;
        d = &Bs[0][kc1*128 + mr1]; d[0]=pb1.x; d[128]=pb1.y; d[256]=pb1.z; d[384]=pb1.w;
    }
    __syncthreads();

    for (int kt = 0; kt < ntk; ++kt) {
        const bool have_next = (kt + 1 < ntk);
        if (have_next) {
            const int off = (kt + 1) << 4;
            pa0 = *(const float4*)(Ap0 + off);
            pa1 = *(const float4*)(Ap1 + off);
            pb0 = *(const float4*)(Bp0 + off);
            pb1 = *(const float4*)(Bp1 + off);
        }

        const float* __restrict__ Ab = As[buf];
        const float* __restrict__ Bb = Bs[buf];
#pragma unroll
        for (int kk = 0; kk < 16; ++kk) {
            // B fragment: 4 packed pairs (8 cols), two 128-bit LDS.
            const ulonglong2 b0 = *(const ulonglong2*)&Bb[kk*128 + tx*4];
            const ulonglong2 b1 = *(const ulonglong2*)&Bb[kk*128 + 64 + tx*4];
            // A fragment: 8 dup-packed rows via four broadcast LDS.128.
            const ulonglong2 A01 = *(const ulonglong2*)&Ab[kk*256 + ty*16];
            const ulonglong2 A23 = *(const ulonglong2*)&Ab[kk*256 + ty*16 + 4];
            const ulonglong2 A45 = *(const ulonglong2*)&Ab[kk*256 + ty*16 + 8];
            const ulonglong2 A67 = *(const ulonglong2*)&Ab[kk*256 + ty*16 + 12];
            const unsigned long long aa[8] =
                {A01.x, A01.y, A23.x, A23.y, A45.x, A45.y, A67.x, A67.y};
#pragma unroll
            for (int r = 0; r < 8; ++r) {
                ffma2(acc[r][0], aa[r], b0.x);
                ffma2(acc[r][1], aa[r], b0.y);
                ffma2(acc[r][2], aa[r], b1.x);
                ffma2(acc[r][3], aa[r], b1.y);
            }
        }

        if (have_next) {
            const int nb = buf ^ 1;
            float2* d2;
            float*  d;
            d2 = (float2*)&As[nb][kc0*256 + mr0*2];
            d2[0]   = make_float2(pa0.x, pa0.x); d2[128] = make_float2(pa0.y, pa0.y);
            d2[256] = make_float2(pa0.z, pa0.z); d2[384] = make_float2(pa0.w, pa0.w);
            d2 = (float2*)&As[nb][kc1*256 + mr1*2];
            d2[0]   = make_float2(pa1.x, pa1.x); d2[128] = make_float2(pa1.y, pa1.y);
            d2[256] = make_float2(pa1.z, pa1.z); d2[384] = make_float2(pa1.w, pa1.w);
            d = &Bs[nb][kc0*128 + mr0]; d[0]=pb0.x; d[128]=pb0.y; d[256]=pb0.z; d[384]=pb0.w;
            d = &Bs[nb][kc1*128 + mr1]; d[0]=pb1.x; d[128]=pb1.y; d[256]=pb1.z; d[384]=pb1.w;
            __syncthreads();
            buf = nb;
        }
    }

    // Epilogue: pairs (c,c+1),(c+2,c+3) are contiguous -> 128-bit stores.
#pragma unroll
    for (int r = 0; r < 8; ++r) {
        float* c = C + (size_t)(tm + ty*8 + r) * N + tn;
        ulonglong2 lo; lo.x = acc[r][0]; lo.y = acc[r][1];
        ulonglong2 hi; hi.x = acc[r][2]; hi.y = acc[r][3];
        *(ulonglong2*)(c + tx*4)      = lo;
        *(ulonglong2*)(c + 64 + tx*4) = hi;
    }
}

// Fused QKV: gridDim.z = 3 picks the weight + destination. One launch lets
// Wk/Wv tiles fill the Wq tail waves (removes 2 inter-launch bubbles).
__global__ __launch_bounds__(256) void sgemm_qkv(const float* __restrict__ A,
                                                 const float* __restrict__ W0,
                                                 const float* __restrict__ W1,
                                                 const float* __restrict__ W2,
                                                 float* __restrict__ C0,
                                                 float* __restrict__ C1,
                                                 float* __restrict__ C2,
                                                 int M, int N, int K)
{
    __shared__ float As[2][16*256];   // A duplicated: 32 KB
    __shared__ float Bs[2][16*128];   // 16 KB  (total 48 KB, 2 CTAs/SM)
    const int z = blockIdx.z;
    const float* Bw = (z == 0) ? W0 : (z == 1) ? W1 : W2;
    float*       C  = (z == 0) ? C0 : (z == 1) ? C1 : C2;
    sgemm_tile(A, Bw, C, M, N, K, blockIdx.y * 128, blockIdx.x * 128, As, Bs);
}

// Single GEMM (output projection)
__global__ __launch_bounds__(256) void sgemm_nt(const float* __restrict__ A,
                                                const float* __restrict__ Bw,
                                                float* __restrict__ C,
                                                int M, int N, int K)
{
    __shared__ float As[2][16*256];
    __shared__ float Bs[2][16*128];
    sgemm_tile(A, Bw, C, M, N, K, blockIdx.y * 128, blockIdx.x * 128, As, Bs);
}

// ---------------------------------------------------------------------------
// Flash attention (causal), fp32, packed f32x2 FMA.  Grid: (S/64, B*H).
// 256 threads.  BQ = 64, BK = 32, DH = 128.  ~84 KB smem -> 2 CTAs/SM.
// blockIdx.x -> qt map REVERSED (longest-first; shrinks ragged tail).
// Causal mask via GLOBAL indices (col_g > row_g) -> no tile edge cases.
// Q/K tiles XOR-swizzled (granule ^= row&7) -> conflict-free LDS.128.
// K/V tile kt=0 L2-prefetched BEFORE the Q load; tile kt+1 during compute.
// sP stored DUPLICATED (pitch 72 floats): PV reads ready-packed (p,p) pairs
// via LDS.128 -> zero pack MOVs in PV.
// sP producer set == consumer set per 16-lane half-warp -> __syncwarp between
// softmax and PV; 2 full barriers per tile instead of 3.
// Thread (ty,tx): score cols {tx, tx+16}; O cols {tx*4..+3, 64+tx*4..+3}.
// ---------------------------------------------------------------------------
#define SP_PITCH 72
#define FLASH_SMEM_FLOATS (64*128 + 2*32*128 + 64*SP_PITCH)   // 20992 ~ 84KB

__global__ __launch_bounds__(256, 2) void flash_attn(const float* __restrict__ Qg,
                                                     const float* __restrict__ Kg,
                                                     const float* __restrict__ Vg,
                                                     float* __restrict__ Octx)
{
    extern __shared__ float sm[];
    float* sQ = sm;                  // 64*128, swizzled
    float* sK = sm + 64*128;         // 32*128, swizzled
    float* sV = sm + 64*128 + 32*128;// 32*128, row-major
    float* sP = sm + 64*128 + 2*32*128; // 64*SP_PITCH, duplicated pairs

    const int tid = threadIdx.x;
    const int ty  = tid >> 4;
    const int tx  = tid & 15;
    const int ty4 = ty * 4;
    const int qt  = gridDim.x - 1 - blockIdx.x;   // longest-first scheduling
    const int bh  = blockIdx.y;
    const int b   = bh >> 4;
    const int h   = bh & 15;

    const float* qbase = Qg + (size_t)b*Sq*Dq + h*DHh;
    const float* kbase = Kg + (size_t)b*Sq*Dq + h*DHh;
    const float* vbase = Vg + (size_t)b*Sq*Dq + h*DHh;

    // Warm L2 with the FIRST K/V tile before the Q load occupies the LSU.
#pragma unroll
    for (int it = 0; it < 4; ++it) {
        const int lin = tid + it*256;
        const int r   = lin >> 5;
        const int dd  = (lin & 31) << 2;
        prefetch_l2(kbase + (size_t)r*Dq + dd);
        prefetch_l2(vbase + (size_t)r*Dq + dd);
    }

    // Load Q tile once (swizzled): 64 rows x 32 f4
#pragma unroll
    for (int it = 0; it < 8; ++it) {
        const int lin = tid + it*256;      // float4 index, 2048 total
        const int r   = lin >> 5;          // 32 f4 per row
        const int dd  = (lin & 31) << 2;
        const int g   = dd >> 2;
        const float4 v = *(const float4*)(qbase + (size_t)(qt*64 + r)*Dq + dd);
        *(float4*)&sQ[r*128 + ((g ^ (r & 7)) << 2)] = v;
    }

    // O accumulators: 4 rows x 4 packed pairs (cols tx*4..+3, 64+tx*4..+3)
    unsigned long long oacc[4][4];
    float mrow[4], lrow[4];
#pragma unroll
    for (int i = 0; i < 4; ++i) {
#pragma unroll
        for (int p = 0; p < 4; ++p) oacc[i][p] = 0ull;
        mrow[i] = -INFINITY;
        lrow[i] = 0.f;
    }

    const int nkt = 2*qt + 2;       // k-tiles of 32 rows covering 0..qt*64+63
    for (int kt = 0; kt < nkt; ++kt) {
        // Load K (swizzled) and V (row-major) tiles: 32 rows x 32 f4 each
#pragma unroll
        for (int it = 0; it < 4; ++it) {
            const int lin = tid + it*256;  // 1024 f4 per tile
            const int r   = lin >> 5;
            const int dd  = (lin & 31) << 2;
            const int g   = dd >> 2;
            const float4 kv = *(const float4*)(kbase + (size_t)(kt*32 + r)*Dq + dd);
            *(float4*)&sK[r*128 + ((g ^ (r & 7)) << 2)] = kv;
            const float4 vv = *(const float4*)(vbase + (size_t)(kt*32 + r)*Dq + dd);
            *(float4*)&sV[r*128 + dd] = vv;
        }
        // L2-prefetch next tile's K/V lines (hidden behind this tile's compute)
        if (kt + 1 < nkt) {
#pragma unroll
            for (int it = 0; it < 4; ++it) {
                const int lin = tid + it*256;
                const int r   = lin >> 5;
                const int dd  = (lin & 31) << 2;
                prefetch_l2(kbase + (size_t)((kt+1)*32 + r)*Dq + dd);
                prefetch_l2(vbase + (size_t)((kt+1)*32 + r)*Dq + dd);
            }
        }
        __syncthreads();

        // --- scores: s[i][j] = dot(q_row, k_col) over DH=128, packed pairs ---
        unsigned long long s2[4][2];
#pragma unroll
        for (int i = 0; i < 4; ++i) { s2[i][0] = 0ull; s2[i][1] = 0ull; }

#pragma unroll
        for (int dd = 0; dd < 128; dd += 4) {
            const int g = dd >> 2;
            ulonglong2 qf[4], kf[2];
#pragma unroll
            for (int i = 0; i < 4; ++i) {
                const int r = ty4 + i;
                qf[i] = *(const ulonglong2*)&sQ[r*128 + ((g ^ (r & 7)) << 2)];
            }
#pragma unroll
            for (int j = 0; j < 2; ++j) {
                const int c = tx + 16*j;
                kf[j] = *(const ulonglong2*)&sK[c*128 + ((g ^ (c & 7)) << 2)];
            }
#pragma unroll
            for (int i = 0; i < 4; ++i)
#pragma unroll
                for (int j = 0; j < 2; ++j) {
                    ffma2(s2[i][j], qf[i].x, kf[j].x);
                    ffma2(s2[i][j], qf[i].y, kf[j].y);
                }
        }

        // --- online softmax (rows owned by 16 lanes with same ty) ---
#pragma unroll
        for (int i = 0; i < 4; ++i) {
            const int rowg = qt*64 + ty4 + i;
            float sv[2];
            float tmax = -INFINITY;
#pragma unroll
            for (int j = 0; j < 2; ++j) {
                const float2 p = unpack2(s2[i][j]);
                float v = (p.x + p.y) * SCALE_F;
                if (kt*32 + tx + 16*j > rowg) v = -INFINITY;   // global causal mask
                sv[j] = v;
                tmax = fmaxf(tmax, v);
            }
#pragma unroll
            for (int off = 8; off > 0; off >>= 1)
                tmax = fmaxf(tmax, __shfl_xor_sync(0xffffffffu, tmax, off));

            const float newm  = fmaxf(mrow[i], tmax);
            const float alpha = __expf(mrow[i] - newm);
            mrow[i] = newm;

            float rs = 0.f;
#pragma unroll
            for (int j = 0; j < 2; ++j) {
                const float pv = __expf(sv[j] - newm);   // masked -> exp(-inf)=0
                // duplicated store: ready-packed (p,p) for PV's f32x2 FMA
                *(float2*)&sP[(ty4 + i)*SP_PITCH + (tx + 16*j)*2] = make_float2(pv, pv);
                rs += pv;
            }
#pragma unroll
            for (int off = 8; off > 0; off >>= 1)
                rs += __shfl_xor_sync(0xffffffffu, rs, off);
            lrow[i] = lrow[i]*alpha + rs;

            const unsigned long long a2 = pack2_bcast(alpha);
#pragma unroll
            for (int p = 0; p < 4; ++p) oacc[i][p] = mul2(oacc[i][p], a2);
        }
        // sP rows ty4..ty4+3 are produced and consumed by the SAME 16-lane
        // half-warp (both sets depend only on ty) -> warp-level sync suffices.
        __syncwarp();

        // --- PV: O += P @ V (packed f32x2; sP dup-pairs via LDS.128) ---
#pragma unroll 4
        for (int k4 = 0; k4 < 32; k4 += 4) {
            ulonglong2 pd0[4], pd1[4];
#pragma unroll
            for (int i = 0; i < 4; ++i) {
                pd0[i] = *(const ulonglong2*)&sP[(ty4 + i)*SP_PITCH + k4*2];
                pd1[i] = *(const ulonglong2*)&sP[(ty4 + i)*SP_PITCH + k4*2 + 4];
            }
#pragma unroll
            for (int u = 0; u < 4; ++u) {
                const int kk = k4 + u;
                const ulonglong2 vlo = *(const ulonglong2*)&sV[kk*128 + tx*4];
                const ulonglong2 vhi = *(const ulonglong2*)&sV[kk*128 + 64 + tx*4];
#pragma unroll
                for (int i = 0; i < 4; ++i) {
                    const unsigned long long p2 =
                        (u == 0) ? pd0[i].x : (u == 1) ? pd0[i].y
                      : (u == 2) ? pd1[i].x : pd1[i].y;
                    ffma2(oacc[i][0], p2, vlo.x);
                    ffma2(oacc[i][1], p2, vlo.y);
                    ffma2(oacc[i][2], p2, vhi.x);
                    ffma2(oacc[i][3], p2, vhi.y);
                }
            }
        }
        __syncthreads();   // protects sK/sV (and sP) against next-tile overwrite
    }

    // --- epilogue: normalize and store ctx[b][s][h*128 + c] ---
#pragma unroll
    for (int i = 0; i < 4; ++i) {
        const unsigned long long inv2 = pack2_bcast(1.0f / lrow[i]);
        const int qg = qt*64 + ty4 + i;
        float* out = Octx + (size_t)(b*Sq + qg)*Dq + h*DHh;
        ulonglong2 lo, hi;
        lo.x = mul2(oacc[i][0], inv2); lo.y = mul2(oacc[i][1], inv2);
        hi.x = mul2(oacc[i][2], inv2); hi.y = mul2(oacc[i][3], inv2);
        *(ulonglong2*)(out + tx*4)      = lo;
        *(ulonglong2*)(out + 64 + tx*4) = hi;
    }
}

// ---------------------------------------------------------------------------
extern "C" void kernel_launch(void* const* d_in, const int* in_sizes, int n_in,
                              void* d_out, int out_size)
{
    const float* x  = (const float*)d_in[0];
    const float* Wq = (const float*)d_in[1];
    const float* Wk = (const float*)d_in[2];
    const float* Wv = (const float*)d_in[3];
    const float* Wo = (const float*)d_in[4];
    float* out = (float*)d_out;

    float *q, *k, *v, *ctx;
    cudaGetSymbolAddress((void**)&q,   g_q);
    cudaGetSymbolAddress((void**)&k,   g_k);
    cudaGetSymbolAddress((void**)&v,   g_v);
    cudaGetSymbolAddress((void**)&ctx, g_ctx);

    const int flash_smem = FLASH_SMEM_FLOATS * (int)sizeof(float);  // ~84 KB
    cudaFuncSetAttribute(flash_attn, cudaFuncAttributeMaxDynamicSharedMemorySize,
                         flash_smem);

    // QKV projections fused into one launch: grid (16, 32, 3)
    sgemm_qkv<<<dim3(Dq/128, MSZ/128, 3), 256>>>(x, Wq, Wk, Wv, q, k, v,
                                                 MSZ, Dq, Dq);

    // Causal attention with scale = sqrt(DH) (faithful to reference)
    flash_attn<<<dim3(Sq/64, Bq*Hh), 256, flash_smem>>>(q, k, v, ctx);

    // Output projection
    sgemm_nt<<<dim3(Dq/128, MSZ/128), 256>>>(ctx, Wo, out, MSZ, Dq, Dq);
}

// round 16
// speedup vs baseline: 1.0091x; 1.0091x over previous
#include <cuda_runtime.h>
#include <math.h>

// Problem constants
#define Bq  4
#define Sq  1024
#define Dq  2048
#define Hh  16
#define DHh 128
#define MSZ (Bq*Sq)          // 4096 rows
#define SCALE_F 11.3137084989847603904f   // sqrt(128)

// Scratch (allocation-free rule: __device__ globals)
__device__ float g_q[MSZ*Dq];
__device__ float g_k[MSZ*Dq];
__device__ float g_v[MSZ*Dq];
__device__ float g_ctx[MSZ*Dq];

// ---------------------------------------------------------------------------
// Packed fp32x2 helpers (Blackwell sm_10x; exact fp32 semantics per lane).
// ---------------------------------------------------------------------------
__device__ __forceinline__ unsigned long long pack2_bcast(float v) {
    unsigned long long r;
    asm("mov.b64 %0, {%1, %1};" : "=l"(r) : "f"(v));
    return r;
}
__device__ __forceinline__ void ffma2(unsigned long long& d,
                                      unsigned long long a,
                                      unsigned long long b) {
    asm("fma.rn.f32x2 %0, %1, %2, %0;" : "+l"(d) : "l"(a), "l"(b));
}
__device__ __forceinline__ unsigned long long mul2(unsigned long long a,
                                                   unsigned long long b) {
    unsigned long long d;
    asm("mul.rn.f32x2 %0, %1, %2;" : "=l"(d) : "l"(a), "l"(b));
    return d;
}
__device__ __forceinline__ float2 unpack2(unsigned long long v) {
    float lo, hi;
    asm("mov.b64 {%0, %1}, %2;" : "=f"(lo), "=f"(hi) : "l"(v));
    return make_float2(lo, hi);
}
__device__ __forceinline__ void prefetch_l2(const void* p) {
    asm volatile("prefetch.global.L2 [%0];" :: "l"(p));
}

// ---------------------------------------------------------------------------
// Core SGEMM NT tile: C[M,N] = A[M,K] * B[N,K]^T  (row-major, K contiguous)
// 128x128 block tile, BK=16, 256 threads, 8x8 per-thread microtile.
// Double-buffered smem ping-pong (one __syncthreads per k-tile).
// A tile stored DUPLICATED in smem: one LDS.128 yields two ready-packed (a,a)
// f32x2 operands -> inner loop is 32 FFMA2 + 6 LDS.128 per kk, zero pack MOVs.
// __launch_bounds__(256,2) caps regs at 128 -> 2 CTAs/SM (measured: 142 regs
// forced 1 CTA/SM, occ=12.5%, fma=48.9% -- latency exposed).
// ---------------------------------------------------------------------------
__device__ __forceinline__ void sgemm_tile(const float* __restrict__ A,
                                           const float* __restrict__ Bw,
                                           float* __restrict__ C,
                                           int M, int N, int K,
                                           int tm, int tn,
                                           float (*As)[16*256], float (*Bs)[16*128])
{
    const int tid = threadIdx.x;
    const int ty  = tid >> 4;
    const int tx  = tid & 15;

    // Loader mapping: 512 float4 per tile per matrix; 2 per thread.
    const int lin0 = tid;
    const int lin1 = tid + 256;
    const int mr0 = lin0 >> 2, kc0 = (lin0 & 3) << 2;
    const int mr1 = lin1 >> 2, kc1 = (lin1 & 3) << 2;

    const float* Ap0 = A  + (size_t)(tm + mr0) * K + kc0;
    const float* Ap1 = A  + (size_t)(tm + mr1) * K + kc1;
    const float* Bp0 = Bw + (size_t)(tn + mr0) * K + kc0;
    const float* Bp1 = Bw + (size_t)(tn + mr1) * K + kc1;

    // 8 rows x 4 column-pairs (cols tx*4..+3 and 64+tx*4..+3), packed f32x2.
    unsigned long long acc[8][4];
#pragma unroll
    for (int r = 0; r < 8; ++r)
#pragma unroll
        for (int p = 0; p < 4; ++p) acc[r][p] = 0ull;   // (0.f,0.f)

    // Prefetch tile 0 into registers
    float4 pa0 = *(const float4*)Ap0;
    float4 pa1 = *(const float4*)Ap1;
    float4 pb0 = *(const float4*)Bp0;
    float4 pb1 = *(const float4*)Bp1;

    const int ntk = K >> 4;
    int buf = 0;
    {
        float2* d2;
        float*  d;
        d2 = (float2*)&As[0][kc0*256 + mr0*2];
        d2[0]   = make_float2(pa0.x, pa0.x); d2[128] = make_float2(pa0.y, pa0.y);
        d2[256] = make_float2(pa0.z, pa0.z); d2[384] = make_float2(pa0.w, pa0.w);
        d2 = (float2*)&As[0][kc1*256 + mr1*2];
        d2[0]   = make_float2(pa1.x, pa1.x); d2[128] = make_float2(pa1.y, pa1.y);
        d2[256] = make_float2(pa1.z, pa1.z); d2[384] = make_float2(pa1.w, pa1.w);
        d = &Bs[0][kc0*128 + mr0]; d[0]=pb0.x; d[128]=pb0.y; d[256]=pb0.z; d[384]=pb0.w;
        d = &Bs[0][kc1*128 + mr1]; d[0]=pb1.x; d[128]=pb1.y; d[256]=pb1.z; d[384]=pb1.w;
    }
    __syncthreads();

    for (int kt = 0; kt < ntk; ++kt) {
        const bool have_next = (kt + 1 < ntk);
        if (have_next) {
            const int off = (kt + 1) << 4;
            pa0 = *(const float4*)(Ap0 + off);
            pa1 = *(const float4*)(Ap1 + off);
            pb0 = *(const float4*)(Bp0 + off);
            pb1 = *(const float4*)(Bp1 + off);
        }

        const float* __restrict__ Ab = As[buf];
        const float* __restrict__ Bb = Bs[buf];
#pragma unroll
        for (int kk = 0; kk < 16; ++kk) {
            // B fragment: 4 packed pairs (8 cols), two 128-bit LDS.
            const ulonglong2 b0 = *(const ulonglong2*)&Bb[kk*128 + tx*4];
            const ulonglong2 b1 = *(const ulonglong2*)&Bb[kk*128 + 64 + tx*4];
            // A fragment: 8 dup-packed rows via four broadcast LDS.128.
            const ulonglong2 A01 = *(const ulonglong2*)&Ab[kk*256 + ty*16];
            const ulonglong2 A23 = *(const ulonglong2*)&Ab[kk*256 + ty*16 + 4];
            const ulonglong2 A45 = *(const ulonglong2*)&Ab[kk*256 + ty*16 + 8];
            const ulonglong2 A67 = *(const ulonglong2*)&Ab[kk*256 + ty*16 + 12];
            const unsigned long long aa[8] =
                {A01.x, A01.y, A23.x, A23.y, A45.x, A45.y, A67.x, A67.y};
#pragma unroll
            for (int r = 0; r < 8; ++r) {
                ffma2(acc[r][0], aa[r], b0.x);
                ffma2(acc[r][1], aa[r], b0.y);
                ffma2(acc[r][2], aa[r], b1.x);
                ffma2(acc[r][3], aa[r], b1.y);
            }
        }

        if (have_next) {
            const int nb = buf ^ 1;
            float2* d2;
            float*  d;
            d2 = (float2*)&As[nb][kc0*256 + mr0*2];
            d2[0]   = make_float2(pa0.x, pa0.x); d2[128] = make_float2(pa0.y, pa0.y);
            d2[256] = make_float2(pa0.z, pa0.z); d2[384] = make_float2(pa0.w, pa0.w);
            d2 = (float2*)&As[nb][kc1*256 + mr1*2];
            d2[0]   = make_float2(pa1.x, pa1.x); d2[128] = make_float2(pa1.y, pa1.y);
            d2[256] = make_float2(pa1.z, pa1.z); d2[384] = make_float2(pa1.w, pa1.w);
            d = &Bs[nb][kc0*128 + mr0]; d[0]=pb0.x; d[128]=pb0.y; d[256]=pb0.z; d[384]=pb0.w;
            d = &Bs[nb][kc1*128 + mr1]; d[0]=pb1.x; d[128]=pb1.y; d[256]=pb1.z; d[384]=pb1.w;
            __syncthreads();
            buf = nb;
        }
    }

    // Epilogue: pairs (c,c+1),(c+2,c+3) are contiguous -> 128-bit stores.
#pragma unroll
    for (int r = 0; r < 8; ++r) {
        float* c = C + (size_t)(tm + ty*8 + r) * N + tn;
        ulonglong2 lo; lo.x = acc[r][0]; lo.y = acc[r][1];
        ulonglong2 hi; hi.x = acc[r][2]; hi.y = acc[r][3];
        *(ulonglong2*)(c + tx*4)      = lo;
        *(ulonglong2*)(c + 64 + tx*4) = hi;
    }
}

// Fused QKV: gridDim.z = 3 picks the weight + destination.
__global__ __launch_bounds__(256, 2) void sgemm_qkv(const float* __restrict__ A,
                                                    const float* __restrict__ W0,
                                                    const float* __restrict__ W1,
                                                    const float* __restrict__ W2,
                                                    float* __restrict__ C0,
                                                    float* __restrict__ C1,
                                                    float* __restrict__ C2,
                                                    int M, int N, int K)
{
    __shared__ float As[2][16*256];   // A duplicated: 32 KB
    __shared__ float Bs[2][16*128];   // 16 KB  (total 48 KB, 2 CTAs/SM)
    const int z = blockIdx.z;
    const float* Bw = (z == 0) ? W0 : (z == 1) ? W1 : W2;
    float*       C  = (z == 0) ? C0 : (z == 1) ? C1 : C2;
    sgemm_tile(A, Bw, C, M, N, K, blockIdx.y * 128, blockIdx.x * 128, As, Bs);
}

// Single GEMM (output projection)
__global__ __launch_bounds__(256, 2) void sgemm_nt(const float* __restrict__ A,
                                                   const float* __restrict__ Bw,
                                                   float* __restrict__ C,
                                                   int M, int N, int K)
{
    __shared__ float As[2][16*256];
    __shared__ float Bs[2][16*128];
    sgemm_tile(A, Bw, C, M, N, K, blockIdx.y * 128, blockIdx.x * 128, As, Bs);
}

// ---------------------------------------------------------------------------
// Flash attention (causal), fp32, packed f32x2 FMA.  Grid: (S/64, B*H).
// 256 threads.  BQ = 64, BK = 32, DH = 128.  ~84 KB smem -> 2 CTAs/SM.
// blockIdx.x -> qt map REVERSED (longest-first; shrinks ragged tail).
// Causal mask via GLOBAL indices (col_g > row_g) -> no tile edge cases.
// Q/K tiles XOR-swizzled (granule ^= row&7) -> conflict-free LDS.128.
// K/V tile kt=0 L2-prefetched BEFORE the Q load; tile kt+1 during compute.
// sP stored DUPLICATED (pitch 72 floats): PV reads ready-packed (p,p) pairs.
// sP producer set == consumer set per 16-lane half-warp -> __syncwarp.
// ---------------------------------------------------------------------------
#define SP_PITCH 72
#define FLASH_SMEM_FLOATS (64*128 + 2*32*128 + 64*SP_PITCH)   // 20992 ~ 84KB

__global__ __launch_bounds__(256, 2) void flash_attn(const float* __restrict__ Qg,
                                                     const float* __restrict__ Kg,
                                                     const float* __restrict__ Vg,
                                                     float* __restrict__ Octx)
{
    extern __shared__ float sm[];
    float* sQ = sm;                  // 64*128, swizzled
    float* sK = sm + 64*128;         // 32*128, swizzled
    float* sV = sm + 64*128 + 32*128;// 32*128, row-major
    float* sP = sm + 64*128 + 2*32*128; // 64*SP_PITCH, duplicated pairs

    const int tid = threadIdx.x;
    const int ty  = tid >> 4;
    const int tx  = tid & 15;
    const int ty4 = ty * 4;
    const int qt  = gridDim.x - 1 - blockIdx.x;   // longest-first scheduling
    const int bh  = blockIdx.y;
    const int b   = bh >> 4;
    const int h   = bh & 15;

    const float* qbase = Qg + (size_t)b*Sq*Dq + h*DHh;
    const float* kbase = Kg + (size_t)b*Sq*Dq + h*DHh;
    const float* vbase = Vg + (size_t)b*Sq*Dq + h*DHh;

    // Warm L2 with the FIRST K/V tile before the Q load occupies the LSU.
#pragma unroll
    for (int it = 0; it < 4; ++it) {
        const int lin = tid + it*256;
        const int r   = lin >> 5;
        const int dd  = (lin & 31) << 2;
        prefetch_l2(kbase + (size_t)r*Dq + dd);
        prefetch_l2(vbase + (size_t)r*Dq + dd);
    }

    // Load Q tile once (swizzled): 64 rows x 32 f4
#pragma unroll
    for (int it = 0; it < 8; ++it) {
        const int lin = tid + it*256;      // float4 index, 2048 total
        const int r   = lin >> 5;          // 32 f4 per row
        const int dd  = (lin & 31) << 2;
        const int g   = dd >> 2;
        const float4 v = *(const float4*)(qbase + (size_t)(qt*64 + r)*Dq + dd);
        *(float4*)&sQ[r*128 + ((g ^ (r & 7)) << 2)] = v;
    }

    // O accumulators: 4 rows x 4 packed pairs (cols tx*4..+3, 64+tx*4..+3)
    unsigned long long oacc[4][4];
    float mrow[4], lrow[4];
#pragma unroll
    for (int i = 0; i < 4; ++i) {
#pragma unroll
        for (int p = 0; p < 4; ++p) oacc[i][p] = 0ull;
        mrow[i] = -INFINITY;
        lrow[i] = 0.f;
    }

    const int nkt = 2*qt + 2;       // k-tiles of 32 rows covering 0..qt*64+63
    for (int kt = 0; kt < nkt; ++kt) {
        // Load K (swizzled) and V (row-major) tiles: 32 rows x 32 f4 each
#pragma unroll
        for (int it = 0; it < 4; ++it) {
            const int lin = tid + it*256;  // 1024 f4 per tile
            const int r   = lin >> 5;
            const int dd  = (lin & 31) << 2;
            const int g   = dd >> 2;
            const float4 kv = *(const float4*)(kbase + (size_t)(kt*32 + r)*Dq + dd);
            *(float4*)&sK[r*128 + ((g ^ (r & 7)) << 2)] = kv;
            const float4 vv = *(const float4*)(vbase + (size_t)(kt*32 + r)*Dq + dd);
            *(float4*)&sV[r*128 + dd] = vv;
        }
        // L2-prefetch next tile's K/V lines (hidden behind this tile's compute)
        if (kt + 1 < nkt) {
#pragma unroll
            for (int it = 0; it < 4; ++it) {
                const int lin = tid + it*256;
                const int r   = lin >> 5;
                const int dd  = (lin & 31) << 2;
                prefetch_l2(kbase + (size_t)((kt+1)*32 + r)*Dq + dd);
                prefetch_l2(vbase + (size_t)((kt+1)*32 + r)*Dq + dd);
            }
        }
        __syncthreads();

        // --- scores: s[i][j] = dot(q_row, k_col) over DH=128, packed pairs ---
        unsigned long long s2[4][2];
#pragma unroll
        for (int i = 0; i < 4; ++i) { s2[i][0] = 0ull; s2[i][1] = 0ull; }

#pragma unroll
        for (int dd = 0; dd < 128; dd += 4) {
            const int g = dd >> 2;
            ulonglong2 qf[4], kf[2];
#pragma unroll
            for (int i = 0; i < 4; ++i) {
                const int r = ty4 + i;
                qf[i] = *(const ulonglong2*)&sQ[r*128 + ((g ^ (r & 7)) << 2)];
            }
#pragma unroll
            for (int j = 0; j < 2; ++j) {
                const int c = tx + 16*j;
                kf[j] = *(const ulonglong2*)&sK[c*128 + ((g ^ (c & 7)) << 2)];
            }
#pragma unroll
            for (int i = 0; i < 4; ++i)
#pragma unroll
                for (int j = 0; j < 2; ++j) {
                    ffma2(s2[i][j], qf[i].x, kf[j].x);
                    ffma2(s2[i][j], qf[i].y, kf[j].y);
                }
        }

        // --- online softmax (rows owned by 16 lanes with same ty) ---
#pragma unroll
        for (int i = 0; i < 4; ++i) {
            const int rowg = qt*64 + ty4 + i;
            float sv[2];
            float tmax = -INFINITY;
#pragma unroll
            for (int j = 0; j < 2; ++j) {
                const float2 p = unpack2(s2[i][j]);
                float v = (p.x + p.y) * SCALE_F;
                if (kt*32 + tx + 16*j > rowg) v = -INFINITY;   // global causal mask
                sv[j] = v;
                tmax = fmaxf(tmax, v);
            }
#pragma unroll
            for (int off = 8; off > 0; off >>= 1)
                tmax = fmaxf(tmax, __shfl_xor_sync(0xffffffffu, tmax, off));

            const float newm  = fmaxf(mrow[i], tmax);
            const float alpha = __expf(mrow[i] - newm);
            mrow[i] = newm;

            float rs = 0.f;
#pragma unroll
            for (int j = 0; j < 2; ++j) {
                const float pv = __expf(sv[j] - newm);   // masked -> exp(-inf)=0
                *(float2*)&sP[(ty4 + i)*SP_PITCH + (tx + 16*j)*2] = make_float2(pv, pv);
                rs += pv;
            }
#pragma unroll
            for (int off = 8; off > 0; off >>= 1)
                rs += __shfl_xor_sync(0xffffffffu, rs, off);
            lrow[i] = lrow[i]*alpha + rs;

            const unsigned long long a2 = pack2_bcast(alpha);
#pragma unroll
            for (int p = 0; p < 4; ++p) oacc[i][p] = mul2(oacc[i][p], a2);
        }
        __syncwarp();

        // --- PV: O += P @ V (packed f32x2; sP dup-pairs via LDS.128) ---
#pragma unroll 4
        for (int k4 = 0; k4 < 32; k4 += 4) {
            ulonglong2 pd0[4], pd1[4];
#pragma unroll
            for (int i = 0; i < 4; ++i) {
                pd0[i] = *(const ulonglong2*)&sP[(ty4 + i)*SP_PITCH + k4*2];
                pd1[i] = *(const ulonglong2*)&sP[(ty4 + i)*SP_PITCH + k4*2 + 4];
            }
#pragma unroll
            for (int u = 0; u < 4; ++u) {
                const int kk = k4 + u;
                const ulonglong2 vlo = *(const ulonglong2*)&sV[kk*128 + tx*4];
                const ulonglong2 vhi = *(const ulonglong2*)&sV[kk*128 + 64 + tx*4];
#pragma unroll
                for (int i = 0; i < 4; ++i) {
                    const unsigned long long p2 =
                        (u == 0) ? pd0[i].x : (u == 1) ? pd0[i].y
                      : (u == 2) ? pd1[i].x : pd1[i].y;
                    ffma2(oacc[i][0], p2, vlo.x);
                    ffma2(oacc[i][1], p2, vlo.y);
                    ffma2(oacc[i][2], p2, vhi.x);
                    ffma2(oacc[i][3], p2, vhi.y);
                }
            }
        }
        __syncthreads();   // protects sK/sV (and sP) against next-tile overwrite
    }

    // --- epilogue: normalize and store ctx[b][s][h*128 + c] ---
#pragma unroll
    for (int i = 0; i < 4; ++i) {
        const unsigned long long inv2 = pack2_bcast(1.0f / lrow[i]);
        const int qg = qt*64 + ty4 + i;
        float* out = Octx + (size_t)(b*Sq + qg)*Dq + h*DHh;
        ulonglong2 lo, hi;
        lo.x = mul2(oacc[i][0], inv2); lo.y = mul2(oacc[i][1], inv2);
        hi.x = mul2(oacc[i][2], inv2); hi.y = mul2(oacc[i][3], inv2);
        *(ulonglong2*)(out + tx*4)      = lo;
        *(ulonglong2*)(out + 64 + tx*4) = hi;
    }
}

// ---------------------------------------------------------------------------
extern "C" void kernel_launch(void* const* d_in, const int* in_sizes, int n_in,
                              void* d_out, int out_size)
{
    const float* x  = (const float*)d_in[0];
    const float* Wq = (const float*)d_in[1];
    const float* Wk = (const float*)d_in[2];
    const float* Wv = (const float*)d_in[3];
    const float* Wo = (const float*)d_in[4];
    float* out = (float*)d_out;

    float *q, *k, *v, *ctx;
    cudaGetSymbolAddress((void**)&q,   g_q);
    cudaGetSymbolAddress((void**)&k,   g_k);
    cudaGetSymbolAddress((void**)&v,   g_v);
    cudaGetSymbolAddress((void**)&ctx, g_ctx);

    const int flash_smem = FLASH_SMEM_FLOATS * (int)sizeof(float);  // ~84 KB
    cudaFuncSetAttribute(flash_attn, cudaFuncAttributeMaxDynamicSharedMemorySize,
                         flash_smem);

    // QKV projections fused into one launch: grid (16, 32, 3)
    sgemm_qkv<<<dim3(Dq/128, MSZ/128, 3), 256>>>(x, Wq, Wk, Wv, q, k, v,
                                                 MSZ, Dq, Dq);

    // Causal attention with scale = sqrt(DH) (faithful to reference)
    flash_attn<<<dim3(Sq/64, Bq*Hh), 256, flash_smem>>>(q, k, v, ctx);

    // Output projection
    sgemm_nt<<<dim3(Dq/128, MSZ/128), 256>>>(ctx, Wo, out, MSZ, Dq, Dq);
}